// round 5
// baseline (speedup 1.0000x reference)
#include <cuda_runtime.h>
#include <cstdint>

// Problem dims
#define NB 32
#define C  64
#define H  128
#define W  128
#define CO 64
#define HO 64
#define WO 64

// Scratch: packed sign bits.
__device__ uint64_t g_xpack[NB * H * W];          // 4 MiB
__device__ uint64_t g_wpack[CO * 9];

// ---------------------------------------------------------------------------
// Kernel 1: pack x AND w sign bits. Blocks 0..1023 pack x (2 px/thread);
// block 1024 packs w (runs concurrently, latency fully hidden under x-pack).
// ---------------------------------------------------------------------------
__global__ __launch_bounds__(256) void pack_kernel(const float* __restrict__ x,
                                                   const float* __restrict__ w) {
    if (blockIdx.x == 1024) {
        // ---- pack w: 576 (co,tap) words, 64 scattered loads each ----
        for (int t = threadIdx.x; t < CO * 9; t += 256) {
            int co = t / 9;
            int k  = t - co * 9;
            uint32_t lo = 0, hi = 0;
            #pragma unroll 8
            for (int ci = 0; ci < 32; ++ci)
                lo |= (uint32_t)(w[(size_t)(co * 64 + ci) * 9 + k] >= 0.0f) << ci;
            #pragma unroll 8
            for (int ci = 0; ci < 32; ++ci)
                hi |= (uint32_t)(w[(size_t)(co * 64 + ci + 32) * 9 + k] >= 0.0f) << ci;
            g_wpack[t] = (uint64_t)lo | ((uint64_t)hi << 32);
        }
        return;
    }

    int tid = blockIdx.x * blockDim.x + threadIdx.x;   // 0 .. 262143
    int w2 = tid & 63;            // group of 2 pixels along w
    int h  = (tid >> 6) & 127;
    int n  = tid >> 13;

    const float* base = x + (size_t)n * C * (H * W) + h * W + w2 * 2;

    uint32_t lo0 = 0, lo1 = 0, hi0 = 0, hi1 = 0;

    #pragma unroll 16
    for (int c = 0; c < 32; ++c) {
        float2 v = *reinterpret_cast<const float2*>(base + (size_t)c * (H * W));
        lo0 |= (uint32_t)(v.x >= 0.0f) << c;
        lo1 |= (uint32_t)(v.y >= 0.0f) << c;
    }
    #pragma unroll 16
    for (int c = 0; c < 32; ++c) {
        float2 v = *reinterpret_cast<const float2*>(base + (size_t)(c + 32) * (H * W));
        hi0 |= (uint32_t)(v.x >= 0.0f) << c;
        hi1 |= (uint32_t)(v.y >= 0.0f) << c;
    }

    uint64_t* op = g_xpack + ((size_t)n * H + h) * W + w2 * 2;
    op[0] = (uint64_t)lo0 | ((uint64_t)hi0 << 32);
    op[1] = (uint64_t)lo1 | ((uint64_t)hi1 << 32);
}

// Full adder over bit-columns: popc(a)+popc(b)+popc(c) == popc(s) + 2*popc(cy).
// s = one LOP3 (0x96), cy = majority = one LOP3 (0xE8).
__device__ __forceinline__ void fa(uint32_t a, uint32_t b, uint32_t c,
                                   uint32_t& s, uint32_t& cy) {
    s  = a ^ b ^ c;
    cy = (a & b) | (a & c) | (b & c);
}

// ---------------------------------------------------------------------------
// Kernel 2: XNOR-popcount conv with CSA compression.
// Grid: (16 ho-groups, NB, 2 co-halves). 256 threads: tx=wo, ty=local ho.
// Per (pixel, co): 18 masked-XOR words are compressed by a 3:2 CSA tree to
// 6 words (weights 1,1,2,2,4,8) -> 6 POPC instead of 18.
// ---------------------------------------------------------------------------
__global__ __launch_bounds__(256) void qconv_kernel(float* __restrict__ out) {
    const int PW = 132;
    __shared__ uint64_t sw[32 * 9];
    __shared__ uint64_t sp[9 * 132];

    int n   = blockIdx.y;
    int ho0 = blockIdx.x * 4;
    int coh = blockIdx.z * 32;
    int iy0 = 2 * ho0 - 1;

    for (int i = threadIdx.x; i < 9 * 129; i += 256) {
        int r  = i / 129;
        int cx = i - r * 129;
        int iy = iy0 + r;
        int ix = cx - 1;
        uint64_t v = 0;
        if (iy >= 0 && ix >= 0)
            v = g_xpack[((size_t)n * H + iy) * W + ix];
        sp[r * PW + cx] = v;
    }
    for (int i = threadIdx.x; i < 32 * 9; i += 256)
        sw[i] = g_wpack[coh * 9 + i];
    __syncthreads();

    int tx = threadIdx.x & 63;    // wo
    int ty = threadIdx.x >> 6;    // local ho
    int ho = ho0 + ty;

    uint32_t slo[9], shi[9], msk[9];
    #pragma unroll
    for (int ky = 0; ky < 3; ++ky) {
        #pragma unroll
        for (int kx = 0; kx < 3; ++kx) {
            int t = ky * 3 + kx;
            uint64_t s = sp[(2 * ty + ky) * PW + 2 * tx + kx];
            slo[t] = (uint32_t)s;
            shi[t] = (uint32_t)(s >> 32);
            bool valid = (ho > 0 || ky > 0) && (tx > 0 || kx > 0);
            msk[t] = valid ? 0xFFFFFFFFu : 0u;
        }
    }
    int nvalid = (ho > 0 ? 3 : 2) * (tx > 0 ? 3 : 2);
    int base   = 64 * nvalid;

    float* op = out + (((size_t)n * CO + coh) * HO + ho) * WO + tx;

    #pragma unroll 2
    for (int co = 0; co < 32; ++co) {
        const uint64_t* wrow = sw + co * 9;

        // 18 masked XNOR-difference words
        uint32_t v[18];
        #pragma unroll
        for (int t = 0; t < 9; ++t) {
            uint64_t wv = wrow[t];                 // warp-uniform broadcast LDS
            v[2 * t]     = (slo[t] ^ (uint32_t)wv) & msk[t];
            v[2 * t + 1] = (shi[t] ^ (uint32_t)(wv >> 32)) & msk[t];
        }

        // CSA tree: 18 -> {w1: sA,sB}, {w2: t2,cB}, {w4: q3}, {w8: o0}
        uint32_t S[6], Cc[6];
        #pragma unroll
        for (int g = 0; g < 6; ++g)
            fa(v[3 * g], v[3 * g + 1], v[3 * g + 2], S[g], Cc[g]);

        uint32_t sA, cA, sB, cB;
        fa(S[0], S[1], S[2], sA, cA);
        fa(S[3], S[4], S[5], sB, cB);

        uint32_t t0, q0, t1, q1;
        fa(Cc[0], Cc[1], Cc[2], t0, q0);
        fa(Cc[3], Cc[4], Cc[5], t1, q1);

        uint32_t t2, q2;
        fa(t0, t1, cA, t2, q2);

        uint32_t q3, o0;
        fa(q0, q1, q2, q3, o0);

        int acc = __popc(sA) + __popc(sB)
                + 2 * (__popc(t2) + __popc(cB))
                + 4 * __popc(q3)
                + 8 * __popc(o0);

        op[(size_t)co * (HO * WO)] = (float)(base - 2 * acc);
    }
}

// ---------------------------------------------------------------------------
extern "C" void kernel_launch(void* const* d_in, const int* in_sizes, int n_in,
                              void* d_out, int out_size) {
    const float* x = (const float*)d_in[0];
    const float* w = (const float*)d_in[1];
    float* out = (float*)d_out;

    pack_kernel<<<1025, 256>>>(x, w);
    qconv_kernel<<<dim3(16, NB, 2), 256>>>(out);
}